// round 4
// baseline (speedup 1.0000x reference)
#include <cuda_runtime.h>
#include <cuda_bf16.h>
#include <math.h>

#define N_NODES 100000
#define N_EDGES 1600000
#define C 64
#define MAXL 512           // max in-degree of a pair node (Poisson(16): P(>512)~0)
#define MAXF 1026          // 2 + 2*MAXL
#define GRID 592           // 4 blocks/SM on 148 SMs -> guaranteed co-resident
#define TPB 256

// ---------------- device scratch (static, allocation-free) ----------------
__device__ int   g_is32;
__device__ int   g_deg[N_NODES];
__device__ int   g_slot[N_NODES];      // -1 = not in frontier, else slot id
__device__ int   g_listA[MAXL];
__device__ int   g_listB[MAXL];
__device__ int   g_cntA, g_cntB, g_nfront;
__device__ int   g_frontier[MAXF];
__device__ float g_agg[MAXF * C];      // sum over in-edges of dinv[src]*x[src]
__device__ float g_h1[MAXF * C];
__device__ unsigned g_barcnt;          // zero-initialized at module load
__device__ unsigned g_bargen;

// ---------------- software grid barrier (all GRID blocks resident) --------
__device__ __forceinline__ void gbar() {
    __syncthreads();
    __threadfence();
    if (threadIdx.x == 0) {
        unsigned gen = ((volatile unsigned*)&g_bargen)[0];
        if (atomicAdd(&g_barcnt, 1u) == GRID - 1u) {
            atomicExch(&g_barcnt, 0u);
            __threadfence();
            atomicAdd(&g_bargen, 1u);
        } else {
            while (((volatile unsigned*)&g_bargen)[0] == gen) { }
        }
    }
    __syncthreads();
}

__device__ __forceinline__ int idx_at(const void* p, long long i, int is32) {
    if (is32) return ((const int*)p)[i];
    return (int)(((const long long*)p)[i]);
}

__device__ __forceinline__ void fr_insert(int v) {
    if ((unsigned)v >= N_NODES) return;
    if (atomicCAS(&g_slot[v], -1, -2) == -1) {
        int s = atomicAdd(&g_nfront, 1);
        if (s < MAXF) { g_frontier[s] = v; g_slot[v] = s; }
    }
}

__device__ __forceinline__ void load_dst4(const void* edge, long long base,
                                          int is32, int d[4]) {
    if (is32) {
        const int* dp = (const int*)edge + N_EDGES;
        int4 t = *(const int4*)(dp + base);
        d[0] = t.x; d[1] = t.y; d[2] = t.z; d[3] = t.w;
    } else {
        const long long* dp = (const long long*)edge + N_EDGES;
        longlong2 a = *(const longlong2*)(dp + base);
        longlong2 b = *(const longlong2*)(dp + base + 2);
        d[0] = (int)a.x; d[1] = (int)a.y; d[2] = (int)b.x; d[3] = (int)b.y;
    }
}

// ---------------- the whole pipeline, one launch ----------------
__global__ __launch_bounds__(TPB)
void k_fused(const float* __restrict__ x,
             const void*  __restrict__ edge,
             const void*  __restrict__ pair,
             const float* __restrict__ W1,
             const float* __restrict__ b1,
             const float* __restrict__ W2,
             const float* __restrict__ b2,
             const float* __restrict__ fcW,
             const float* __restrict__ fcb,
             float* __restrict__ out) {
    const int tid  = threadIdx.x;
    const int bid  = blockIdx.x;
    const int gt   = bid * TPB + tid;
    const int nthr = GRID * TPB;

    // ---- P0: init + dtype sniff ----
    for (int i = gt; i < N_NODES; i += nthr) { g_deg[i] = 0; g_slot[i] = -1; }
    for (int i = gt; i < MAXF * C; i += nthr) g_agg[i] = 0.0f;
    if (gt == 0) {
        g_cntA = 0; g_cntB = 0; g_nfront = 0;
        const long long* e = (const long long*)edge;
        int is32 = 0;
        #pragma unroll
        for (int k = 0; k < 16; k++) {
            long long v = e[k];
            if (v < 0 || v >= N_NODES) { is32 = 1; break; }
        }
        g_is32 = is32;
    }
    gbar();

    const int is32 = __ldcg(&g_is32);
    const int p0 = idx_at(pair, 0, is32);
    const int p1 = idx_at(pair, 1, is32);
    if (gt == 0) fr_insert(p0);
    if (gt == 1) fr_insert(p1);

    // ---- P1: scan dst -> degrees + pair lists + frontier ----
    for (long long e4 = gt; e4 < N_EDGES / 4; e4 += nthr) {
        long long base = e4 * 4;
        int d[4];
        load_dst4(edge, base, is32, d);
        #pragma unroll
        for (int k = 0; k < 4; k++) {
            int dd = d[k];
            if ((unsigned)dd >= N_NODES) continue;
            atomicAdd(&g_deg[dd], 1);
            if (dd == p0 || dd == p1) {
                int s = idx_at(edge, base + k, is32);
                if ((unsigned)s >= N_NODES) continue;
                if (dd == p0) {
                    int j = atomicAdd(&g_cntA, 1);
                    if (j < MAXL) g_listA[j] = s;
                }
                if (dd == p1) {
                    int j = atomicAdd(&g_cntB, 1);
                    if (j < MAXL) g_listB[j] = s;
                }
                fr_insert(s);
            }
        }
    }
    gbar();

    // ---- P2: scan dst -> fused layer-1 aggregation ----
    // edge (s -> d in frontier): agg[slot(d)] += rsqrt(deg[s]+1) * x[s]
    for (long long e4 = gt; e4 < N_EDGES / 4; e4 += nthr) {
        long long base = e4 * 4;
        int d[4];
        load_dst4(edge, base, is32, d);
        #pragma unroll
        for (int k = 0; k < 4; k++) {
            int dd = d[k];
            if ((unsigned)dd >= N_NODES) continue;
            int sl = __ldcg(&g_slot[dd]);
            if (sl >= 0 && sl < MAXF) {
                int s = idx_at(edge, base + k, is32);
                if ((unsigned)s >= N_NODES) continue;
                float w = rsqrtf((float)(__ldcg(&g_deg[s]) + 1));
                const float4* xr = (const float4*)(x + (size_t)s * C);
                float* ag = g_agg + (size_t)sl * C;
                #pragma unroll
                for (int c4 = 0; c4 < C / 4; c4++) {
                    float4 v = __ldg(xr + c4);
                    atomicAdd(ag + 4 * c4 + 0, w * v.x);
                    atomicAdd(ag + 4 * c4 + 1, w * v.y);
                    atomicAdd(ag + 4 * c4 + 2, w * v.z);
                    atomicAdd(ag + 4 * c4 + 3, w * v.w);
                }
            }
        }
    }
    gbar();

    // ---- P3: layer-1 matvec per frontier node ----
    {
        int nf = min(__ldcg(&g_nfront), MAXF);
        __shared__ float sy[C];
        for (int s = bid; s < nf; s += GRID) {
            int v = __ldcg(&g_frontier[s]);
            float dv = rsqrtf((float)(__ldcg(&g_deg[v]) + 1));
            if (tid < C) {
                float y = dv * __ldcg(&g_agg[s * C + tid])
                        + dv * dv * __ldg(&x[(size_t)v * C + tid]);
                sy[tid] = y;
            }
            __syncthreads();
            if (tid < C) {
                float acc = b1[tid];
                #pragma unroll
                for (int k = 0; k < C; k++) acc += sy[k] * W1[k * C + tid];
                g_h1[s * C + tid] = fmaxf(acc, 0.0f);
            }
            __syncthreads();
        }
    }
    gbar();

    // ---- P4: layer-2 + fc + sigmoid (block 0 only) ----
    if (bid == 0) {
        __shared__ float sz[2 * C];
        __shared__ float sh2[2 * C];
        int t = tid;
        if (t < 2 * C) {
            int p = t >> 6;
            int c = t & (C - 1);
            int v = (p == 0) ? p0 : p1;
            float z = 0.0f;
            if ((unsigned)v < N_NODES) {
                float dv = rsqrtf((float)(__ldcg(&g_deg[v]) + 1));
                int sv = __ldcg(&g_slot[v]);
                if (sv >= 0 && sv < MAXF) z = dv * dv * __ldcg(&g_h1[sv * C + c]);
                int cnt = (p == 0) ? min(__ldcg(&g_cntA), MAXL)
                                   : min(__ldcg(&g_cntB), MAXL);
                const int* list = (p == 0) ? g_listA : g_listB;
                for (int j = 0; j < cnt; j++) {
                    int u = __ldcg(&list[j]);
                    int su = __ldcg(&g_slot[u]);
                    if (su >= 0 && su < MAXF)
                        z += rsqrtf((float)(__ldcg(&g_deg[u]) + 1)) * dv
                           * __ldcg(&g_h1[su * C + c]);
                }
            }
            sz[t] = z;
        }
        __syncthreads();
        if (t < 2 * C) {
            int p = t >> 6;
            int c = t & (C - 1);
            float acc = b2[c];
            #pragma unroll
            for (int k = 0; k < C; k++) acc += sz[p * C + k] * W2[k * C + c];
            sh2[t] = fmaxf(acc, 0.0f) * fcW[t];
        }
        __syncthreads();
        for (int s = C; s > 0; s >>= 1) {
            if (t < s) sh2[t] += sh2[t + s];
            __syncthreads();
        }
        if (t == 0) out[0] = 1.0f / (1.0f + expf(-(sh2[0] + fcb[0])));
    }
}

// ---------------- launch ----------------
extern "C" void kernel_launch(void* const* d_in, const int* in_sizes, int n_in,
                              void* d_out, int out_size) {
    const float* x    = (const float*)d_in[0];
    const void*  edge = d_in[1];
    const void*  pair = d_in[2];
    const float* W1   = (const float*)d_in[3];
    const float* b1   = (const float*)d_in[4];
    const float* W2   = (const float*)d_in[5];
    const float* b2   = (const float*)d_in[6];
    const float* fcW  = (const float*)d_in[7];
    const float* fcb  = (const float*)d_in[8];
    float* out = (float*)d_out;

    k_fused<<<GRID, TPB>>>(x, edge, pair, W1, b1, W2, b2, fcW, fcb, out);
}